// round 5
// baseline (speedup 1.0000x reference)
#include <cuda_runtime.h>
#include <cstdint>

#define BATCH 4096
#define DIM   1024
#define NC    1000
#define NTOT  5096
#define NPAD  5120
#define EPSF 1e-8f
#define QSCALE 512.0f
#define ISCALE (10.0f / (QSCALE * QSCALE))   // acc_int -> sim/tau

#define BM 128
#define BN 128
#define LDB 80                    // bytes per smem row: 64 data + 16 pad
#define NBLK (NPAD / BN)          // 40
#define NFB  (BATCH / BM)         // 32
#define NTILE 784                 // upper-triangle tiles

// ---- scratch ----
__device__ __align__(16) signed char g_G[(size_t)NPAD * DIM];  // s8, x*512
__device__ float g_w[NPAD];
__device__ int   g_cls[NPAD];
__device__ int   g_counts[NC];
__device__ float g_dexp[BATCH];                   // exact exp(10*||f_i||^2)
__device__ float g_dpart[NBLK * BATCH];
__device__ float g_ppart[NBLK * BATCH];

// ---------------- prep kernels ----------------
__global__ void k_zero_counts() {
    if (threadIdx.x < NC) g_counts[threadIdx.x] = 0;
}

__global__ void k_count(const int* __restrict__ targets) {
    int i = blockIdx.x * blockDim.x + threadIdx.x;
    if (i < BATCH) atomicAdd(&g_counts[targets[i]], 1);
}

__global__ void k_wcls(const int* __restrict__ targets) {
    int k = blockIdx.x * blockDim.x + threadIdx.x;
    if (k >= NPAD) return;
    if (k < BATCH) {
        int t = targets[k];
        g_w[k]   = 1.0f / (float)(g_counts[t] + 1);
        g_cls[k] = t;
    } else if (k < NTOT) {
        int j = k - BATCH;
        g_w[k]   = 1.0f / (float)(g_counts[j] + 1);
        g_cls[k] = j;
    } else {
        g_w[k]   = 0.0f;
        g_cls[k] = -1;
    }
}

__device__ __forceinline__ uint32_t quant4(float4 v) {
    int a = max(-127, min(127, __float2int_rn(v.x * QSCALE)));
    int b = max(-127, min(127, __float2int_rn(v.y * QSCALE)));
    int c = max(-127, min(127, __float2int_rn(v.z * QSCALE)));
    int d = max(-127, min(127, __float2int_rn(v.w * QSCALE)));
    return (uint32_t)(a & 0xff) | ((uint32_t)(b & 0xff) << 8) |
           ((uint32_t)(c & 0xff) << 16) | ((uint32_t)(d & 0xff) << 24);
}

// fp32 -> s8 (x512), 16 elems (16B out) per thread
__global__ void k_convert(const float* __restrict__ features,
                          const float* __restrict__ centers) {
    int idx = blockIdx.x * blockDim.x + threadIdx.x;   // 0 .. NPAD*DIM/16-1
    if (idx >= NPAD * DIM / 16) return;
    int row  = idx >> 6;
    int col0 = (idx & 63) << 4;

    float4 v[4];
    if (row < BATCH) {
        const float4* p = reinterpret_cast<const float4*>(features + (size_t)row * DIM + col0);
#pragma unroll
        for (int t = 0; t < 4; t++) v[t] = p[t];
    } else if (row < NTOT) {
        const float4* p = reinterpret_cast<const float4*>(centers + (size_t)(row - BATCH) * DIM + col0);
#pragma unroll
        for (int t = 0; t < 4; t++) v[t] = p[t];
    } else {
#pragma unroll
        for (int t = 0; t < 4; t++) v[t] = make_float4(0.f, 0.f, 0.f, 0.f);
    }
    uint4 pk;
    pk.x = quant4(v[0]); pk.y = quant4(v[1]); pk.z = quant4(v[2]); pk.w = quant4(v[3]);
    *reinterpret_cast<uint4*>(g_G + (size_t)row * DIM + col0) = pk;
}

// exact fp32 diagonal: g_dexp[i] = exp(10 * ||f_i||^2)
__global__ void k_diagexp(const float* __restrict__ features) {
    int row  = blockIdx.x * 8 + (threadIdx.x >> 5);
    int lane = threadIdx.x & 31;
    const float4* p = reinterpret_cast<const float4*>(features + (size_t)row * DIM);
    float s = 0.0f;
#pragma unroll
    for (int k = 0; k < 8; k++) {
        float4 v = p[k * 32 + lane];
        s += v.x * v.x + v.y * v.y + v.z * v.z + v.w * v.w;
    }
#pragma unroll
    for (int m = 16; m > 0; m >>= 1) s += __shfl_xor_sync(0xffffffffu, s, m);
    if (lane == 0) g_dexp[row] = __expf(s * 10.0f);
}

// ---------------- mma helpers ----------------
__device__ __forceinline__ void ldmatrix_x4(uint32_t& r0, uint32_t& r1, uint32_t& r2, uint32_t& r3,
                                            uint32_t addr) {
    asm volatile("ldmatrix.sync.aligned.m8n8.x4.shared.b16 {%0,%1,%2,%3}, [%4];"
                 : "=r"(r0), "=r"(r1), "=r"(r2), "=r"(r3) : "r"(addr));
}
__device__ __forceinline__ void ldmatrix_x2(uint32_t& r0, uint32_t& r1, uint32_t addr) {
    asm volatile("ldmatrix.sync.aligned.m8n8.x2.shared.b16 {%0,%1}, [%2];"
                 : "=r"(r0), "=r"(r1) : "r"(addr));
}
__device__ __forceinline__ void mma_s8(int* c, uint32_t a0, uint32_t a1, uint32_t a2, uint32_t a3,
                                       uint32_t b0, uint32_t b1) {
    asm volatile(
        "mma.sync.aligned.m16n8k32.row.col.s32.s8.s8.s32 "
        "{%0,%1,%2,%3}, {%4,%5,%6,%7}, {%8,%9}, {%0,%1,%2,%3};"
        : "+r"(c[0]), "+r"(c[1]), "+r"(c[2]), "+r"(c[3])
        : "r"(a0), "r"(a1), "r"(a2), "r"(a3), "r"(b0), "r"(b1));
}

// ---------------- fused INT8 GEMM + dual-role epilogue ----------------
__global__ __launch_bounds__(256) void k_gemm() {
    int t = blockIdx.x;
    int bm = 0;
    while (t >= NBLK - bm) { t -= NBLK - bm; bm++; }
    const int bn = bm + t;

    __shared__ __align__(16) unsigned char sA[2][BM * LDB];
    __shared__ __align__(16) unsigned char sB[2][BN * LDB];
    __shared__ float red_d[BM];
    __shared__ float red_p[BM];
    __shared__ float cred_d[BN];
    __shared__ float cred_p[BN];
    __shared__ float sWr[BM];
    __shared__ float sDexp[BM];

    const int tid  = threadIdx.x;
    const int warp = tid >> 5;
    const int lane = tid & 31;
    const int wm = warp >> 2;
    const int wn = warp & 3;
    const int rowBase = bm * BM;
    const int colBase = bn * BN;
    const bool doTrans = (bn > bm) && (bn < NFB);
    const bool diagBlk = (bn == bm);

    if (tid < BM) {
        red_d[tid] = 0.0f; red_p[tid] = 0.0f;
        cred_d[tid] = 0.0f; cred_p[tid] = 0.0f;
        sWr[tid] = g_w[rowBase + tid];
        sDexp[tid] = diagBlk ? g_dexp[rowBase + tid] : 0.0f;
    }

    int acc[4][4][4];
#pragma unroll
    for (int a = 0; a < 4; a++)
#pragma unroll
        for (int b = 0; b < 4; b++)
#pragma unroll
            for (int c = 0; c < 4; c++) acc[a][b][c] = 0;

    const uint4* gG = reinterpret_cast<const uint4*>(g_G);   // row stride = 64 uint4
    const int r0 = tid >> 2;
    const int r1 = r0 + 64;
    const int q  = tid & 3;

    {
        uint4 pa0 = gG[(size_t)(rowBase + r0) * 64 + q];
        uint4 pa1 = gG[(size_t)(rowBase + r1) * 64 + q];
        uint4 pb0 = gG[(size_t)(colBase + r0) * 64 + q];
        uint4 pb1 = gG[(size_t)(colBase + r1) * 64 + q];
        *reinterpret_cast<uint4*>(&sA[0][r0 * LDB + q * 16]) = pa0;
        *reinterpret_cast<uint4*>(&sA[0][r1 * LDB + q * 16]) = pa1;
        *reinterpret_cast<uint4*>(&sB[0][r0 * LDB + q * 16]) = pb0;
        *reinterpret_cast<uint4*>(&sB[0][r1 * LDB + q * 16]) = pb1;
    }
    __syncthreads();

    const int KT = DIM / 64;  // 16 k-chunks of 64 bytes
    const int aOff = (wm * 64 + (lane & 15)) * LDB + (lane >> 4) * 16;
    const int bOff = (wn * 32 + (lane & 7)) * LDB + ((lane >> 3) & 1) * 16;

    for (int kt = 0; kt < KT; kt++) {
        const int cur = kt & 1;
        uint4 pa0, pa1, pb0, pb1;
        if (kt + 1 < KT) {
            const int kq = (kt + 1) * 4;
            pa0 = gG[(size_t)(rowBase + r0) * 64 + kq + q];
            pa1 = gG[(size_t)(rowBase + r1) * 64 + kq + q];
            pb0 = gG[(size_t)(colBase + r0) * 64 + kq + q];
            pb1 = gG[(size_t)(colBase + r1) * 64 + kq + q];
        }

        const uint32_t baseA = (uint32_t)__cvta_generic_to_shared(&sA[cur][0]);
        const uint32_t baseB = (uint32_t)__cvta_generic_to_shared(&sB[cur][0]);

#pragma unroll
        for (int kk = 0; kk < 2; kk++) {
            uint32_t af[4][4];
#pragma unroll
            for (int mt = 0; mt < 4; mt++)
                ldmatrix_x4(af[mt][0], af[mt][1], af[mt][2], af[mt][3],
                            baseA + (uint32_t)(aOff + mt * 16 * LDB + kk * 32));
            uint32_t bf[4][2];
#pragma unroll
            for (int nt = 0; nt < 4; nt++)
                ldmatrix_x2(bf[nt][0], bf[nt][1],
                            baseB + (uint32_t)(bOff + nt * 8 * LDB + kk * 32));
#pragma unroll
            for (int mt = 0; mt < 4; mt++)
#pragma unroll
                for (int nt = 0; nt < 4; nt++)
                    mma_s8(acc[mt][nt], af[mt][0], af[mt][1], af[mt][2], af[mt][3],
                           bf[nt][0], bf[nt][1]);
        }

        if (kt + 1 < KT) {
            const int nxt = cur ^ 1;
            *reinterpret_cast<uint4*>(&sA[nxt][r0 * LDB + q * 16]) = pa0;
            *reinterpret_cast<uint4*>(&sA[nxt][r1 * LDB + q * 16]) = pa1;
            *reinterpret_cast<uint4*>(&sB[nxt][r0 * LDB + q * 16]) = pb0;
            *reinterpret_cast<uint4*>(&sB[nxt][r1 * LDB + q * 16]) = pb1;
            __syncthreads();
        }
    }

    // ---------- epilogue ----------
    const int g = lane >> 2;
    const int tl = lane & 3;

    float wv[4][2];
    int   cl[4][2];
    int   kc[4][2];
#pragma unroll
    for (int nt = 0; nt < 4; nt++)
#pragma unroll
        for (int j = 0; j < 2; j++) {
            int k = colBase + wn * 32 + nt * 8 + tl * 2 + j;
            kc[nt][j] = k;
            wv[nt][j] = g_w[k];
            cl[nt][j] = g_cls[k];
        }

    float cds[4][2], cps[4][2];
#pragma unroll
    for (int nt = 0; nt < 4; nt++)
#pragma unroll
        for (int j = 0; j < 2; j++) { cds[nt][j] = 0.0f; cps[nt][j] = 0.0f; }

#pragma unroll
    for (int mt = 0; mt < 4; mt++) {
#pragma unroll
        for (int h = 0; h < 2; h++) {
            const int lr = wm * 64 + mt * 16 + g + h * 8;
            const int i  = rowBase + lr;
            const int ti = g_cls[i];
            const float wr = sWr[lr];
            float ds = 0.0f, ps = 0.0f;
#pragma unroll
            for (int nt = 0; nt < 4; nt++)
#pragma unroll
                for (int j = 0; j < 2; j++) {
                    float e = __expf((float)acc[mt][nt][h * 2 + j] * ISCALE);
                    if (diagBlk && kc[nt][j] == i) e = sDexp[lr];  // exact self term
                    ds += e * wv[nt][j];
                    float lg = 0.0f;
                    if (cl[nt][j] == ti && kc[nt][j] != i) lg = __logf(e + EPSF);
                    ps += lg;
                    if (doTrans) {
                        cds[nt][j] += e * wr;
                        cps[nt][j] += lg;
                    }
                }
            ds += __shfl_xor_sync(0xffffffffu, ds, 1);
            ds += __shfl_xor_sync(0xffffffffu, ds, 2);
            ps += __shfl_xor_sync(0xffffffffu, ps, 1);
            ps += __shfl_xor_sync(0xffffffffu, ps, 2);
            if (tl == 0) {
                atomicAdd(&red_d[lr], ds);
                atomicAdd(&red_p[lr], ps);
            }
        }
    }

    if (doTrans) {
#pragma unroll
        for (int nt = 0; nt < 4; nt++)
#pragma unroll
            for (int j = 0; j < 2; j++) {
                float v = cds[nt][j], p = cps[nt][j];
                v += __shfl_xor_sync(0xffffffffu, v, 4);
                v += __shfl_xor_sync(0xffffffffu, v, 8);
                v += __shfl_xor_sync(0xffffffffu, v, 16);
                p += __shfl_xor_sync(0xffffffffu, p, 4);
                p += __shfl_xor_sync(0xffffffffu, p, 8);
                p += __shfl_xor_sync(0xffffffffu, p, 16);
                if (g == 0) {
                    const int ck = wn * 32 + nt * 8 + tl * 2 + j;
                    atomicAdd(&cred_d[ck], v);
                    atomicAdd(&cred_p[ck], p);
                }
            }
    }
    __syncthreads();

    if (tid < BM) {
        g_dpart[bn * BATCH + rowBase + tid] = red_d[tid];
        g_ppart[bn * BATCH + rowBase + tid] = red_p[tid];
        if (doTrans) {
            g_dpart[bm * BATCH + colBase + tid] = cred_d[tid];
            g_ppart[bm * BATCH + colBase + tid] = cred_p[tid];
        }
    }
}

// ---------------- finalize ----------------
__global__ void k_final(const int* __restrict__ targets, float* __restrict__ out) {
    __shared__ float sred[1024];
    const int tid = threadIdx.x;
    float local = 0.0f;
    for (int r = tid; r < BATCH; r += 1024) {
        float d = 0.0f, p = 0.0f;
#pragma unroll
        for (int b = 0; b < NBLK; b++) {
            d += g_dpart[b * BATCH + r];
            p += g_ppart[b * BATCH + r];
        }
        const float np = (float)g_counts[targets[r]];
        local += logf(d + EPSF) - p / np;
    }
    sred[tid] = local;
    __syncthreads();
    for (int s = 512; s > 0; s >>= 1) {
        if (tid < s) sred[tid] += sred[tid + s];
        __syncthreads();
    }
    if (tid == 0) out[0] = sred[0] / (float)BATCH;
}

// ---------------- launch ----------------
extern "C" void kernel_launch(void* const* d_in, const int* in_sizes, int n_in,
                              void* d_out, int out_size) {
    const float* centers  = nullptr;
    const float* features = nullptr;
    const int*   targets  = nullptr;
    for (int i = 0; i < n_in; i++) {
        if (in_sizes[i] == BATCH)            targets  = (const int*)d_in[i];
        else if (in_sizes[i] == BATCH * DIM) features = (const float*)d_in[i];
        else if (in_sizes[i] == NC * DIM)    centers  = (const float*)d_in[i];
    }

    k_zero_counts<<<1, 1024>>>();
    k_count<<<(BATCH + 255) / 256, 256>>>(targets);
    k_wcls<<<(NPAD + 255) / 256, 256>>>(targets);
    k_convert<<<(NPAD * DIM / 16 + 255) / 256, 256>>>(features, centers);
    k_diagexp<<<BATCH / 8, 256>>>(features);

    k_gemm<<<NTILE, 256>>>();

    k_final<<<1, 1024>>>(targets, (float*)d_out);
}

// round 7
// speedup vs baseline: 1.9804x; 1.9804x over previous
#include <cuda_runtime.h>
#include <cuda_bf16.h>
#include <cstdint>

#define BATCH 4096
#define DIM   1024
#define NC    1000
#define NTOT  5096
#define NPAD  5120
#define TAU_INV 10.0f
#define EPSF 1e-8f

#define BM 128
#define BN 128
#define BK 32
#define LDA 40              // halves per smem row (32 data + 8 pad)
#define NBLK (NPAD / BN)    // 40
#define NFB  (BATCH / BM)   // 32
#define NTILE 784           // upper-triangle tiles: sum_{bm<32} (40-bm)

// ---- scratch ----
__device__ __nv_bfloat16 g_Gb[NPAD * DIM];
__device__ float g_w[NPAD];
__device__ int   g_cls[NPAD];
__device__ int   g_counts[NC];
__device__ float g_dpart[NBLK * BATCH];
__device__ float g_ppart[NBLK * BATCH];

// ---------------- prep kernels ----------------
__global__ void k_zero_counts() {
    if (threadIdx.x < NC) g_counts[threadIdx.x] = 0;
}

__global__ void k_count(const int* __restrict__ targets) {
    int i = blockIdx.x * blockDim.x + threadIdx.x;
    if (i < BATCH) atomicAdd(&g_counts[targets[i]], 1);
}

__global__ void k_wcls(const int* __restrict__ targets) {
    int k = blockIdx.x * blockDim.x + threadIdx.x;
    if (k >= NPAD) return;
    if (k < BATCH) {
        int t = targets[k];
        g_w[k]   = 1.0f / (float)(g_counts[t] + 1);
        g_cls[k] = t;
    } else if (k < NTOT) {
        int j = k - BATCH;
        g_w[k]   = 1.0f / (float)(g_counts[j] + 1);
        g_cls[k] = j;
    } else {
        g_w[k]   = 0.0f;
        g_cls[k] = -1;
    }
}

__global__ void k_convert(const float* __restrict__ features,
                          const float* __restrict__ centers) {
    int idx = blockIdx.x * blockDim.x + threadIdx.x;
    if (idx >= NPAD * DIM / 8) return;
    int row  = idx >> 7;
    int col0 = (idx & 127) << 3;

    float4 v0, v1;
    if (row < BATCH) {
        const float4* p = reinterpret_cast<const float4*>(features + (size_t)row * DIM + col0);
        v0 = p[0]; v1 = p[1];
    } else if (row < NTOT) {
        const float4* p = reinterpret_cast<const float4*>(centers + (size_t)(row - BATCH) * DIM + col0);
        v0 = p[0]; v1 = p[1];
    } else {
        v0 = make_float4(0.f, 0.f, 0.f, 0.f); v1 = v0;
    }
    __nv_bfloat162 b0 = __nv_bfloat162(__float2bfloat16_rn(v0.x), __float2bfloat16_rn(v0.y));
    __nv_bfloat162 b1 = __nv_bfloat162(__float2bfloat16_rn(v0.z), __float2bfloat16_rn(v0.w));
    __nv_bfloat162 b2 = __nv_bfloat162(__float2bfloat16_rn(v1.x), __float2bfloat16_rn(v1.y));
    __nv_bfloat162 b3 = __nv_bfloat162(__float2bfloat16_rn(v1.z), __float2bfloat16_rn(v1.w));
    uint4 pk;
    pk.x = *reinterpret_cast<uint32_t*>(&b0);
    pk.y = *reinterpret_cast<uint32_t*>(&b1);
    pk.z = *reinterpret_cast<uint32_t*>(&b2);
    pk.w = *reinterpret_cast<uint32_t*>(&b3);
    *reinterpret_cast<uint4*>(g_Gb + (size_t)row * DIM + col0) = pk;
}

// ---------------- helpers ----------------
__device__ __forceinline__ void ldmatrix_x4(uint32_t& r0, uint32_t& r1, uint32_t& r2, uint32_t& r3,
                                            uint32_t addr) {
    asm volatile("ldmatrix.sync.aligned.m8n8.x4.shared.b16 {%0,%1,%2,%3}, [%4];"
                 : "=r"(r0), "=r"(r1), "=r"(r2), "=r"(r3) : "r"(addr));
}
__device__ __forceinline__ void ldmatrix_x2(uint32_t& r0, uint32_t& r1, uint32_t addr) {
    asm volatile("ldmatrix.sync.aligned.m8n8.x2.shared.b16 {%0,%1}, [%2];"
                 : "=r"(r0), "=r"(r1) : "r"(addr));
}
__device__ __forceinline__ void mma16816(float* c, uint32_t a0, uint32_t a1, uint32_t a2, uint32_t a3,
                                         uint32_t b0, uint32_t b1) {
    asm volatile(
        "mma.sync.aligned.m16n8k16.row.col.f32.bf16.bf16.f32 "
        "{%0,%1,%2,%3}, {%4,%5,%6,%7}, {%8,%9}, {%0,%1,%2,%3};"
        : "+f"(c[0]), "+f"(c[1]), "+f"(c[2]), "+f"(c[3])
        : "r"(a0), "r"(a1), "r"(a2), "r"(a3), "r"(b0), "r"(b1));
}
__device__ __forceinline__ void cp16(uint32_t dst, const void* src) {
    asm volatile("cp.async.cg.shared.global [%0], [%1], 16;" :: "r"(dst), "l"(src));
}
#define CP_COMMIT() asm volatile("cp.async.commit_group;")
#define CP_WAIT(n)  asm volatile("cp.async.wait_group %0;" :: "n"(n))

// ---------------- fused GEMM + dual-role epilogue ----------------
__global__ __launch_bounds__(256, 2) void k_gemm() {
    // linear tile id -> upper-triangle (bm, bn)
    int t = blockIdx.x;
    int bm = 0;
    while (t >= NBLK - bm) { t -= NBLK - bm; bm++; }
    const int bn = bm + t;

    __shared__ __align__(16) __nv_bfloat16 sA[2][BM * LDA];
    __shared__ __align__(16) __nv_bfloat16 sB[2][BN * LDA];
    __shared__ float red_d[BM];
    __shared__ float red_p[BM];
    __shared__ float cred_d[BN];
    __shared__ float cred_p[BN];
    __shared__ float sWr[BM];

    const int tid  = threadIdx.x;
    const int warp = tid >> 5;
    const int lane = tid & 31;
    const int wm = warp >> 2;
    const int wn = warp & 3;
    const int rowBase = bm * BM;
    const int colBase = bn * BN;
    const bool doTrans = (bn > bm) && (bn < NFB);

    if (tid < BM) {
        red_d[tid] = 0.0f; red_p[tid] = 0.0f;
        cred_d[tid] = 0.0f; cred_p[tid] = 0.0f;
        sWr[tid] = g_w[rowBase + tid];
    }

    float acc[4][4][4];
#pragma unroll
    for (int a = 0; a < 4; a++)
#pragma unroll
        for (int b = 0; b < 4; b++)
#pragma unroll
            for (int c = 0; c < 4; c++) acc[a][b][c] = 0.0f;

    const int r0 = tid >> 2;            // 0..63
    const int r1 = r0 + 64;
    const int q  = tid & 3;             // 16B chunk
    // global source base pointers (bytes advance by 32 bf16 = 64B per kt... we use uint4 idx)
    const uint4* gA0 = reinterpret_cast<const uint4*>(g_Gb) + (size_t)(rowBase + r0) * (DIM / 8) + q;
    const uint4* gA1 = reinterpret_cast<const uint4*>(g_Gb) + (size_t)(rowBase + r1) * (DIM / 8) + q;
    const uint4* gB0 = reinterpret_cast<const uint4*>(g_Gb) + (size_t)(colBase + r0) * (DIM / 8) + q;
    const uint4* gB1 = reinterpret_cast<const uint4*>(g_Gb) + (size_t)(colBase + r1) * (DIM / 8) + q;

    uint32_t dA0[2], dA1[2], dB0[2], dB1[2];
#pragma unroll
    for (int s = 0; s < 2; s++) {
        dA0[s] = (uint32_t)__cvta_generic_to_shared(&sA[s][r0 * LDA + q * 8]);
        dA1[s] = (uint32_t)__cvta_generic_to_shared(&sA[s][r1 * LDA + q * 8]);
        dB0[s] = (uint32_t)__cvta_generic_to_shared(&sB[s][r0 * LDA + q * 8]);
        dB1[s] = (uint32_t)__cvta_generic_to_shared(&sB[s][r1 * LDA + q * 8]);
    }

    // prologue: stage 0
    cp16(dA0[0], gA0); cp16(dA1[0], gA1);
    cp16(dB0[0], gB0); cp16(dB1[0], gB1);
    CP_COMMIT();

    const int KT = DIM / BK;  // 32
    const int aRow = wm * 64 + (lane & 15);
    const int aCol = (lane >> 4) << 3;
    const int bRow = wn * 32 + (lane & 7);
    const int bCol = ((lane >> 3) & 1) << 3;

    for (int kt = 0; kt < KT; kt++) {
        const int cur = kt & 1;
        if (kt + 1 < KT) {
            const int nxt = cur ^ 1;
            const int kq = (kt + 1) * 4;
            cp16(dA0[nxt], gA0 + kq); cp16(dA1[nxt], gA1 + kq);
            cp16(dB0[nxt], gB0 + kq); cp16(dB1[nxt], gB1 + kq);
            CP_COMMIT();
            CP_WAIT(1);
        } else {
            CP_WAIT(0);
        }
        __syncthreads();

        const uint32_t baseA = (uint32_t)__cvta_generic_to_shared(&sA[cur][0]);
        const uint32_t baseB = (uint32_t)__cvta_generic_to_shared(&sB[cur][0]);

#pragma unroll
        for (int kk = 0; kk < 2; kk++) {
            uint32_t af[4][4];
#pragma unroll
            for (int mt = 0; mt < 4; mt++) {
                uint32_t addr = baseA + (uint32_t)(((aRow + mt * 16) * LDA + kk * 16 + aCol) << 1);
                ldmatrix_x4(af[mt][0], af[mt][1], af[mt][2], af[mt][3], addr);
            }
            uint32_t bf[4][2];
#pragma unroll
            for (int nt = 0; nt < 4; nt++) {
                uint32_t addr = baseB + (uint32_t)(((bRow + nt * 8) * LDA + kk * 16 + bCol) << 1);
                ldmatrix_x2(bf[nt][0], bf[nt][1], addr);
            }
#pragma unroll
            for (int mt = 0; mt < 4; mt++)
#pragma unroll
                for (int nt = 0; nt < 4; nt++)
                    mma16816(acc[mt][nt], af[mt][0], af[mt][1], af[mt][2], af[mt][3],
                             bf[nt][0], bf[nt][1]);
        }
        if (kt + 1 < KT) __syncthreads();   // reads of buf[cur] done before it is re-filled
    }

    // ---------- epilogue ----------
    const int g = lane >> 2;
    const int tl = lane & 3;

    float wv[4][2];
    int   cl[4][2];
    int   kc[4][2];
#pragma unroll
    for (int nt = 0; nt < 4; nt++)
#pragma unroll
        for (int j = 0; j < 2; j++) {
            int k = colBase + wn * 32 + nt * 8 + tl * 2 + j;
            kc[nt][j] = k;
            wv[nt][j] = g_w[k];
            cl[nt][j] = g_cls[k];
        }

    float cds[4][2], cps[4][2];
#pragma unroll
    for (int nt = 0; nt < 4; nt++)
#pragma unroll
        for (int j = 0; j < 2; j++) { cds[nt][j] = 0.0f; cps[nt][j] = 0.0f; }

#pragma unroll
    for (int mt = 0; mt < 4; mt++) {
#pragma unroll
        for (int h = 0; h < 2; h++) {
            const int lr = wm * 64 + mt * 16 + g + h * 8;
            const int i  = rowBase + lr;
            const int ti = g_cls[i];
            const float wr = sWr[lr];
            float ds = 0.0f, ps = 0.0f;
#pragma unroll
            for (int nt = 0; nt < 4; nt++)
#pragma unroll
                for (int j = 0; j < 2; j++) {
                    const float e = __expf(acc[mt][nt][h * 2 + j] * TAU_INV);
                    ds += e * wv[nt][j];
                    float lg = 0.0f;
                    if (cl[nt][j] == ti && kc[nt][j] != i) lg = __logf(e + EPSF);
                    ps += lg;
                    if (doTrans) {
                        cds[nt][j] += e * wr;
                        cps[nt][j] += lg;
                    }
                }
            ds += __shfl_xor_sync(0xffffffffu, ds, 1);
            ds += __shfl_xor_sync(0xffffffffu, ds, 2);
            ps += __shfl_xor_sync(0xffffffffu, ps, 1);
            ps += __shfl_xor_sync(0xffffffffu, ps, 2);
            if (tl == 0) {
                atomicAdd(&red_d[lr], ds);
                atomicAdd(&red_p[lr], ps);
            }
        }
    }

    if (doTrans) {
#pragma unroll
        for (int nt = 0; nt < 4; nt++)
#pragma unroll
            for (int j = 0; j < 2; j++) {
                float v = cds[nt][j], p = cps[nt][j];
                v += __shfl_xor_sync(0xffffffffu, v, 4);
                v += __shfl_xor_sync(0xffffffffu, v, 8);
                v += __shfl_xor_sync(0xffffffffu, v, 16);
                p += __shfl_xor_sync(0xffffffffu, p, 4);
                p += __shfl_xor_sync(0xffffffffu, p, 8);
                p += __shfl_xor_sync(0xffffffffu, p, 16);
                if (g == 0) {
                    const int ck = wn * 32 + nt * 8 + tl * 2 + j;
                    atomicAdd(&cred_d[ck], v);
                    atomicAdd(&cred_p[ck], p);
                }
            }
    }
    __syncthreads();

    if (tid < BM) {
        g_dpart[bn * BATCH + rowBase + tid] = red_d[tid];
        g_ppart[bn * BATCH + rowBase + tid] = red_p[tid];
        if (doTrans) {
            g_dpart[bm * BATCH + colBase + tid] = cred_d[tid];
            g_ppart[bm * BATCH + colBase + tid] = cred_p[tid];
        }
    }
}

// ---------------- finalize ----------------
__global__ void k_final(const int* __restrict__ targets, float* __restrict__ out) {
    __shared__ float sred[1024];
    const int tid = threadIdx.x;
    float local = 0.0f;
    for (int r = tid; r < BATCH; r += 1024) {
        float d = 0.0f, p = 0.0f;
#pragma unroll
        for (int b = 0; b < NBLK; b++) {
            d += g_dpart[b * BATCH + r];
            p += g_ppart[b * BATCH + r];
        }
        const float np = (float)g_counts[targets[r]];
        local += logf(d + EPSF) - p / np;
    }
    sred[tid] = local;
    __syncthreads();
    for (int s = 512; s > 0; s >>= 1) {
        if (tid < s) sred[tid] += sred[tid + s];
        __syncthreads();
    }
    if (tid == 0) out[0] = sred[0] / (float)BATCH;
}

// ---------------- launch ----------------
extern "C" void kernel_launch(void* const* d_in, const int* in_sizes, int n_in,
                              void* d_out, int out_size) {
    const float* centers  = nullptr;
    const float* features = nullptr;
    const int*   targets  = nullptr;
    for (int i = 0; i < n_in; i++) {
        if (in_sizes[i] == BATCH)            targets  = (const int*)d_in[i];
        else if (in_sizes[i] == BATCH * DIM) features = (const float*)d_in[i];
        else if (in_sizes[i] == NC * DIM)    centers  = (const float*)d_in[i];
    }

    k_zero_counts<<<1, 1024>>>();
    k_count<<<(BATCH + 255) / 256, 256>>>(targets);
    k_wcls<<<(NPAD + 255) / 256, 256>>>(targets);
    k_convert<<<(NPAD * DIM / 8 + 255) / 256, 256>>>(features, centers);

    k_gemm<<<NTILE, 256>>>();

    k_final<<<1, 1024>>>(targets, (float*)d_out);
}

// round 8
// speedup vs baseline: 2.0917x; 1.0562x over previous
#include <cuda_runtime.h>
#include <cuda_bf16.h>
#include <cstdint>

#define BATCH 4096
#define DIM   1024
#define NC    1000
#define NTOT  5096
#define NPAD  5120
#define TAU_INV 10.0f
#define EPSF 1e-8f

#define BM 128
#define BN 128
#define BK 32
#define LDA 40              // halves per smem row (32 data + 8 pad)
#define NBLK (NPAD / BN)    // 40
#define NFB  (BATCH / BM)   // 32
#define NTILE 784           // upper-triangle tiles: sum_{bm<32} (40-bm)

// ---- scratch ----
__device__ __nv_bfloat16 g_Gb[NPAD * DIM];
__device__ float g_w[NPAD];
__device__ int   g_cls[NPAD];
__device__ int   g_counts[NC];
__device__ float g_dpart[NBLK * BATCH];
__device__ float g_ppart[NBLK * BATCH];
__device__ float g_rowv[BATCH];

// ---------------- fused prep: counts + weights + classes (1 block) ----------------
__global__ __launch_bounds__(1024) void k_prep(const int* __restrict__ targets) {
    __shared__ int cnt[NC];
    const int tid = threadIdx.x;
    if (tid < NC) cnt[tid] = 0;
    __syncthreads();
#pragma unroll
    for (int i = tid; i < BATCH; i += 1024)
        atomicAdd(&cnt[targets[i]], 1);
    __syncthreads();
    if (tid < NC) g_counts[tid] = cnt[tid];
#pragma unroll
    for (int k = tid; k < NPAD; k += 1024) {
        if (k < BATCH) {
            int t = targets[k];
            g_w[k]   = 1.0f / (float)(cnt[t] + 1);
            g_cls[k] = t;
        } else if (k < NTOT) {
            int j = k - BATCH;
            g_w[k]   = 1.0f / (float)(cnt[j] + 1);
            g_cls[k] = j;
        } else {
            g_w[k]   = 0.0f;
            g_cls[k] = -1;
        }
    }
}

// ---------------- convert: fp32 -> bf16, 16 elems (32B out) per thread ----------------
__global__ void k_convert(const float* __restrict__ features,
                          const float* __restrict__ centers) {
    int idx = blockIdx.x * blockDim.x + threadIdx.x;   // 0 .. NPAD*DIM/16-1
    if (idx >= NPAD * DIM / 16) return;
    int row  = idx >> 6;           // 64 chunks of 16 per row
    int col0 = (idx & 63) << 4;

    float4 v[4];
    if (row < BATCH) {
        const float4* p = reinterpret_cast<const float4*>(features + (size_t)row * DIM + col0);
#pragma unroll
        for (int t = 0; t < 4; t++) v[t] = p[t];
    } else if (row < NTOT) {
        const float4* p = reinterpret_cast<const float4*>(centers + (size_t)(row - BATCH) * DIM + col0);
#pragma unroll
        for (int t = 0; t < 4; t++) v[t] = p[t];
    } else {
#pragma unroll
        for (int t = 0; t < 4; t++) v[t] = make_float4(0.f, 0.f, 0.f, 0.f);
    }
    uint4 pk[2];
    uint32_t* pw = reinterpret_cast<uint32_t*>(pk);
#pragma unroll
    for (int t = 0; t < 4; t++) {
        __nv_bfloat162 lo = __nv_bfloat162(__float2bfloat16_rn(v[t].x), __float2bfloat16_rn(v[t].y));
        __nv_bfloat162 hi = __nv_bfloat162(__float2bfloat16_rn(v[t].z), __float2bfloat16_rn(v[t].w));
        pw[t * 2 + 0] = *reinterpret_cast<uint32_t*>(&lo);
        pw[t * 2 + 1] = *reinterpret_cast<uint32_t*>(&hi);
    }
    uint4* dst = reinterpret_cast<uint4*>(g_Gb + (size_t)row * DIM + col0);
    dst[0] = pk[0];
    dst[1] = pk[1];
}

// ---------------- helpers ----------------
__device__ __forceinline__ void ldmatrix_x4(uint32_t& r0, uint32_t& r1, uint32_t& r2, uint32_t& r3,
                                            uint32_t addr) {
    asm volatile("ldmatrix.sync.aligned.m8n8.x4.shared.b16 {%0,%1,%2,%3}, [%4];"
                 : "=r"(r0), "=r"(r1), "=r"(r2), "=r"(r3) : "r"(addr));
}
__device__ __forceinline__ void ldmatrix_x2(uint32_t& r0, uint32_t& r1, uint32_t addr) {
    asm volatile("ldmatrix.sync.aligned.m8n8.x2.shared.b16 {%0,%1}, [%2];"
                 : "=r"(r0), "=r"(r1) : "r"(addr));
}
__device__ __forceinline__ void mma16816(float* c, uint32_t a0, uint32_t a1, uint32_t a2, uint32_t a3,
                                         uint32_t b0, uint32_t b1) {
    asm volatile(
        "mma.sync.aligned.m16n8k16.row.col.f32.bf16.bf16.f32 "
        "{%0,%1,%2,%3}, {%4,%5,%6,%7}, {%8,%9}, {%0,%1,%2,%3};"
        : "+f"(c[0]), "+f"(c[1]), "+f"(c[2]), "+f"(c[3])
        : "r"(a0), "r"(a1), "r"(a2), "r"(a3), "r"(b0), "r"(b1));
}
__device__ __forceinline__ void cp16(uint32_t dst, const void* src) {
    asm volatile("cp.async.cg.shared.global [%0], [%1], 16;" :: "r"(dst), "l"(src));
}
#define CP_COMMIT() asm volatile("cp.async.commit_group;")
#define CP_WAIT(n)  asm volatile("cp.async.wait_group %0;" :: "n"(n))

// ---------------- fused GEMM + dual-role epilogue (unchanged from R7 win) ----------------
__global__ __launch_bounds__(256, 2) void k_gemm() {
    int t = blockIdx.x;
    int bm = 0;
    while (t >= NBLK - bm) { t -= NBLK - bm; bm++; }
    const int bn = bm + t;

    __shared__ __align__(16) __nv_bfloat16 sA[2][BM * LDA];
    __shared__ __align__(16) __nv_bfloat16 sB[2][BN * LDA];
    __shared__ float red_d[BM];
    __shared__ float red_p[BM];
    __shared__ float cred_d[BN];
    __shared__ float cred_p[BN];
    __shared__ float sWr[BM];

    const int tid  = threadIdx.x;
    const int warp = tid >> 5;
    const int lane = tid & 31;
    const int wm = warp >> 2;
    const int wn = warp & 3;
    const int rowBase = bm * BM;
    const int colBase = bn * BN;
    const bool doTrans = (bn > bm) && (bn < NFB);

    if (tid < BM) {
        red_d[tid] = 0.0f; red_p[tid] = 0.0f;
        cred_d[tid] = 0.0f; cred_p[tid] = 0.0f;
        sWr[tid] = g_w[rowBase + tid];
    }

    float acc[4][4][4];
#pragma unroll
    for (int a = 0; a < 4; a++)
#pragma unroll
        for (int b = 0; b < 4; b++)
#pragma unroll
            for (int c = 0; c < 4; c++) acc[a][b][c] = 0.0f;

    const int r0 = tid >> 2;
    const int r1 = r0 + 64;
    const int q  = tid & 3;
    const uint4* gA0 = reinterpret_cast<const uint4*>(g_Gb) + (size_t)(rowBase + r0) * (DIM / 8) + q;
    const uint4* gA1 = reinterpret_cast<const uint4*>(g_Gb) + (size_t)(rowBase + r1) * (DIM / 8) + q;
    const uint4* gB0 = reinterpret_cast<const uint4*>(g_Gb) + (size_t)(colBase + r0) * (DIM / 8) + q;
    const uint4* gB1 = reinterpret_cast<const uint4*>(g_Gb) + (size_t)(colBase + r1) * (DIM / 8) + q;

    uint32_t dA0[2], dA1[2], dB0[2], dB1[2];
#pragma unroll
    for (int s = 0; s < 2; s++) {
        dA0[s] = (uint32_t)__cvta_generic_to_shared(&sA[s][r0 * LDA + q * 8]);
        dA1[s] = (uint32_t)__cvta_generic_to_shared(&sA[s][r1 * LDA + q * 8]);
        dB0[s] = (uint32_t)__cvta_generic_to_shared(&sB[s][r0 * LDA + q * 8]);
        dB1[s] = (uint32_t)__cvta_generic_to_shared(&sB[s][r1 * LDA + q * 8]);
    }

    cp16(dA0[0], gA0); cp16(dA1[0], gA1);
    cp16(dB0[0], gB0); cp16(dB1[0], gB1);
    CP_COMMIT();

    const int KT = DIM / BK;
    const int aRow = wm * 64 + (lane & 15);
    const int aCol = (lane >> 4) << 3;
    const int bRow = wn * 32 + (lane & 7);
    const int bCol = ((lane >> 3) & 1) << 3;

    for (int kt = 0; kt < KT; kt++) {
        const int cur = kt & 1;
        if (kt + 1 < KT) {
            const int nxt = cur ^ 1;
            const int kq = (kt + 1) * 4;
            cp16(dA0[nxt], gA0 + kq); cp16(dA1[nxt], gA1 + kq);
            cp16(dB0[nxt], gB0 + kq); cp16(dB1[nxt], gB1 + kq);
            CP_COMMIT();
            CP_WAIT(1);
        } else {
            CP_WAIT(0);
        }
        __syncthreads();

        const uint32_t baseA = (uint32_t)__cvta_generic_to_shared(&sA[cur][0]);
        const uint32_t baseB = (uint32_t)__cvta_generic_to_shared(&sB[cur][0]);

#pragma unroll
        for (int kk = 0; kk < 2; kk++) {
            uint32_t af[4][4];
#pragma unroll
            for (int mt = 0; mt < 4; mt++) {
                uint32_t addr = baseA + (uint32_t)(((aRow + mt * 16) * LDA + kk * 16 + aCol) << 1);
                ldmatrix_x4(af[mt][0], af[mt][1], af[mt][2], af[mt][3], addr);
            }
            uint32_t bf[4][2];
#pragma unroll
            for (int nt = 0; nt < 4; nt++) {
                uint32_t addr = baseB + (uint32_t)(((bRow + nt * 8) * LDA + kk * 16 + bCol) << 1);
                ldmatrix_x2(bf[nt][0], bf[nt][1], addr);
            }
#pragma unroll
            for (int mt = 0; mt < 4; mt++)
#pragma unroll
                for (int nt = 0; nt < 4; nt++)
                    mma16816(acc[mt][nt], af[mt][0], af[mt][1], af[mt][2], af[mt][3],
                             bf[nt][0], bf[nt][1]);
        }
        if (kt + 1 < KT) __syncthreads();
    }

    // ---------- epilogue ----------
    const int g = lane >> 2;
    const int tl = lane & 3;

    float wv[4][2];
    int   cl[4][2];
    int   kc[4][2];
#pragma unroll
    for (int nt = 0; nt < 4; nt++)
#pragma unroll
        for (int j = 0; j < 2; j++) {
            int k = colBase + wn * 32 + nt * 8 + tl * 2 + j;
            kc[nt][j] = k;
            wv[nt][j] = g_w[k];
            cl[nt][j] = g_cls[k];
        }

    float cds[4][2], cps[4][2];
#pragma unroll
    for (int nt = 0; nt < 4; nt++)
#pragma unroll
        for (int j = 0; j < 2; j++) { cds[nt][j] = 0.0f; cps[nt][j] = 0.0f; }

#pragma unroll
    for (int mt = 0; mt < 4; mt++) {
#pragma unroll
        for (int h = 0; h < 2; h++) {
            const int lr = wm * 64 + mt * 16 + g + h * 8;
            const int i  = rowBase + lr;
            const int ti = g_cls[i];
            const float wr = sWr[lr];
            float ds = 0.0f, ps = 0.0f;
#pragma unroll
            for (int nt = 0; nt < 4; nt++)
#pragma unroll
                for (int j = 0; j < 2; j++) {
                    const float e = __expf(acc[mt][nt][h * 2 + j] * TAU_INV);
                    ds += e * wv[nt][j];
                    float lg = 0.0f;
                    if (cl[nt][j] == ti && kc[nt][j] != i) lg = __logf(e + EPSF);
                    ps += lg;
                    if (doTrans) {
                        cds[nt][j] += e * wr;
                        cps[nt][j] += lg;
                    }
                }
            ds += __shfl_xor_sync(0xffffffffu, ds, 1);
            ds += __shfl_xor_sync(0xffffffffu, ds, 2);
            ps += __shfl_xor_sync(0xffffffffu, ps, 1);
            ps += __shfl_xor_sync(0xffffffffu, ps, 2);
            if (tl == 0) {
                atomicAdd(&red_d[lr], ds);
                atomicAdd(&red_p[lr], ps);
            }
        }
    }

    if (doTrans) {
#pragma unroll
        for (int nt = 0; nt < 4; nt++)
#pragma unroll
            for (int j = 0; j < 2; j++) {
                float v = cds[nt][j], p = cps[nt][j];
                v += __shfl_xor_sync(0xffffffffu, v, 4);
                v += __shfl_xor_sync(0xffffffffu, v, 8);
                v += __shfl_xor_sync(0xffffffffu, v, 16);
                p += __shfl_xor_sync(0xffffffffu, p, 4);
                p += __shfl_xor_sync(0xffffffffu, p, 8);
                p += __shfl_xor_sync(0xffffffffu, p, 16);
                if (g == 0) {
                    const int ck = wn * 32 + nt * 8 + tl * 2 + j;
                    atomicAdd(&cred_d[ck], v);
                    atomicAdd(&cred_p[ck], p);
                }
            }
    }
    __syncthreads();

    if (tid < BM) {
        g_dpart[bn * BATCH + rowBase + tid] = red_d[tid];
        g_ppart[bn * BATCH + rowBase + tid] = red_p[tid];
        if (doTrans) {
            g_dpart[bm * BATCH + colBase + tid] = cred_d[tid];
            g_ppart[bm * BATCH + colBase + tid] = cred_p[tid];
        }
    }
}

// ---------------- finalize stage 1: per-row (parallel across SMs) ----------------
__global__ void k_final1(const int* __restrict__ targets) {
    const int r = blockIdx.x * blockDim.x + threadIdx.x;   // one row per thread
    if (r >= BATCH) return;
    float d = 0.0f, p = 0.0f;
#pragma unroll
    for (int b = 0; b < NBLK; b++) {
        d += g_dpart[b * BATCH + r];
        p += g_ppart[b * BATCH + r];
    }
    const float np = (float)g_counts[targets[r]];
    g_rowv[r] = logf(d + EPSF) - p / np;
}

// ---------------- finalize stage 2: deterministic tree reduce ----------------
__global__ void k_final2(float* __restrict__ out) {
    __shared__ float sred[1024];
    const int tid = threadIdx.x;
    float local = 0.0f;
    for (int r = tid; r < BATCH; r += 1024) local += g_rowv[r];
    sred[tid] = local;
    __syncthreads();
    for (int s = 512; s > 0; s >>= 1) {
        if (tid < s) sred[tid] += sred[tid + s];
        __syncthreads();
    }
    if (tid == 0) out[0] = sred[0] / (float)BATCH;
}

// ---------------- launch ----------------
extern "C" void kernel_launch(void* const* d_in, const int* in_sizes, int n_in,
                              void* d_out, int out_size) {
    const float* centers  = nullptr;
    const float* features = nullptr;
    const int*   targets  = nullptr;
    for (int i = 0; i < n_in; i++) {
        if (in_sizes[i] == BATCH)            targets  = (const int*)d_in[i];
        else if (in_sizes[i] == BATCH * DIM) features = (const float*)d_in[i];
        else if (in_sizes[i] == NC * DIM)    centers  = (const float*)d_in[i];
    }

    k_prep<<<1, 1024>>>(targets);
    k_convert<<<(NPAD * DIM / 16 + 255) / 256, 256>>>(features, centers);

    k_gemm<<<NTILE, 256>>>();

    k_final1<<<BATCH / 256, 256>>>(targets);
    k_final2<<<1, 1024>>>((float*)d_out);
}

// round 9
// speedup vs baseline: 2.1158x; 1.0115x over previous
#include <cuda_runtime.h>
#include <cuda_bf16.h>
#include <cstdint>

#define BATCH 4096
#define DIM   1024
#define NC    1000
#define NTOT  5096
#define NPAD  5120
#define TAU_INV 10.0f
#define EPSF 1e-8f

#define BM 128
#define BN 128
#define BK 32
#define LDA 40              // halves per smem row (32 data + 8 pad)
#define NBLK (NPAD / BN)    // 40
#define NFB  (BATCH / BM)   // 32
#define NTILE 784           // upper-triangle tiles: sum_{bm<32} (40-bm)

// ---- scratch ----
__device__ __nv_bfloat16 g_Gb[NPAD * DIM];
__device__ float g_w[NPAD];
__device__ int   g_cls[NPAD];
__device__ int   g_counts[NC];
__device__ float g_dpart[NBLK * BATCH];
__device__ float g_ppart[NBLK * BATCH];
__device__ float g_rowv[BATCH];

// ---------------- fused prep: counts + weights + classes (1 block) ----------------
__global__ __launch_bounds__(1024) void k_prep(const int* __restrict__ targets) {
    __shared__ int cnt[NC];
    const int tid = threadIdx.x;
    if (tid < NC) cnt[tid] = 0;
    __syncthreads();
#pragma unroll
    for (int i = tid; i < BATCH; i += 1024)
        atomicAdd(&cnt[targets[i]], 1);
    __syncthreads();
    if (tid < NC) g_counts[tid] = cnt[tid];
#pragma unroll
    for (int k = tid; k < NPAD; k += 1024) {
        if (k < BATCH) {
            int t = targets[k];
            g_w[k]   = 1.0f / (float)(cnt[t] + 1);
            g_cls[k] = t;
        } else if (k < NTOT) {
            int j = k - BATCH;
            g_w[k]   = 1.0f / (float)(cnt[j] + 1);
            g_cls[k] = j;
        } else {
            g_w[k]   = 0.0f;
            g_cls[k] = -1;
        }
    }
}

// ---------------- convert: fp32 -> bf16, 16 elems (32B out) per thread ----------------
__global__ void k_convert(const float* __restrict__ features,
                          const float* __restrict__ centers) {
    int idx = blockIdx.x * blockDim.x + threadIdx.x;   // 0 .. NPAD*DIM/16-1
    if (idx >= NPAD * DIM / 16) return;
    int row  = idx >> 6;           // 64 chunks of 16 per row
    int col0 = (idx & 63) << 4;

    float4 v[4];
    if (row < BATCH) {
        const float4* p = reinterpret_cast<const float4*>(features + (size_t)row * DIM + col0);
#pragma unroll
        for (int t = 0; t < 4; t++) v[t] = p[t];
    } else if (row < NTOT) {
        const float4* p = reinterpret_cast<const float4*>(centers + (size_t)(row - BATCH) * DIM + col0);
#pragma unroll
        for (int t = 0; t < 4; t++) v[t] = p[t];
    } else {
#pragma unroll
        for (int t = 0; t < 4; t++) v[t] = make_float4(0.f, 0.f, 0.f, 0.f);
    }
    uint4 pk[2];
    uint32_t* pw = reinterpret_cast<uint32_t*>(pk);
#pragma unroll
    for (int t = 0; t < 4; t++) {
        __nv_bfloat162 lo = __nv_bfloat162(__float2bfloat16_rn(v[t].x), __float2bfloat16_rn(v[t].y));
        __nv_bfloat162 hi = __nv_bfloat162(__float2bfloat16_rn(v[t].z), __float2bfloat16_rn(v[t].w));
        pw[t * 2 + 0] = *reinterpret_cast<uint32_t*>(&lo);
        pw[t * 2 + 1] = *reinterpret_cast<uint32_t*>(&hi);
    }
    uint4* dst = reinterpret_cast<uint4*>(g_Gb + (size_t)row * DIM + col0);
    dst[0] = pk[0];
    dst[1] = pk[1];
}

// ---------------- helpers ----------------
__device__ __forceinline__ void ldmatrix_x4(uint32_t& r0, uint32_t& r1, uint32_t& r2, uint32_t& r3,
                                            uint32_t addr) {
    asm volatile("ldmatrix.sync.aligned.m8n8.x4.shared.b16 {%0,%1,%2,%3}, [%4];"
                 : "=r"(r0), "=r"(r1), "=r"(r2), "=r"(r3) : "r"(addr));
}
__device__ __forceinline__ void ldmatrix_x2(uint32_t& r0, uint32_t& r1, uint32_t addr) {
    asm volatile("ldmatrix.sync.aligned.m8n8.x2.shared.b16 {%0,%1}, [%2];"
                 : "=r"(r0), "=r"(r1) : "r"(addr));
}
__device__ __forceinline__ void mma16816(float* c, uint32_t a0, uint32_t a1, uint32_t a2, uint32_t a3,
                                         uint32_t b0, uint32_t b1) {
    asm volatile(
        "mma.sync.aligned.m16n8k16.row.col.f32.bf16.bf16.f32 "
        "{%0,%1,%2,%3}, {%4,%5,%6,%7}, {%8,%9}, {%0,%1,%2,%3};"
        : "+f"(c[0]), "+f"(c[1]), "+f"(c[2]), "+f"(c[3])
        : "r"(a0), "r"(a1), "r"(a2), "r"(a3), "r"(b0), "r"(b1));
}
__device__ __forceinline__ void cp16(uint32_t dst, const void* src) {
    asm volatile("cp.async.cg.shared.global [%0], [%1], 16;" :: "r"(dst), "l"(src));
}
#define CP_COMMIT() asm volatile("cp.async.commit_group;")
#define CP_WAIT(n)  asm volatile("cp.async.wait_group %0;" :: "n"(n))

// ---------------- fused GEMM + dual-role epilogue ----------------
__global__ __launch_bounds__(256, 2) void k_gemm() {
    int t = blockIdx.x;
    int bm = 0;
    while (t >= NBLK - bm) { t -= NBLK - bm; bm++; }
    const int bn = bm + t;

    __shared__ __align__(16) __nv_bfloat16 sA[2][BM * LDA];
    __shared__ __align__(16) __nv_bfloat16 sB[2][BN * LDA];
    __shared__ float red_d[BM];
    __shared__ float red_p[BM];
    __shared__ float cred_d[BN];
    __shared__ float cred_p[BN];
    __shared__ float sWr[BM];

    const int tid  = threadIdx.x;
    const int warp = tid >> 5;
    const int lane = tid & 31;
    const int wm = warp >> 2;
    const int wn = warp & 3;
    const int rowBase = bm * BM;
    const int colBase = bn * BN;
    const bool doTrans = (bn > bm) && (bn < NFB);

    if (tid < BM) {
        red_d[tid] = 0.0f; red_p[tid] = 0.0f;
        cred_d[tid] = 0.0f; cred_p[tid] = 0.0f;
        sWr[tid] = g_w[rowBase + tid];
    }

    float acc[4][4][4];
#pragma unroll
    for (int a = 0; a < 4; a++)
#pragma unroll
        for (int b = 0; b < 4; b++)
#pragma unroll
            for (int c = 0; c < 4; c++) acc[a][b][c] = 0.0f;

    const int r0 = tid >> 2;
    const int r1 = r0 + 64;
    const int q  = tid & 3;
    const uint4* gA0 = reinterpret_cast<const uint4*>(g_Gb) + (size_t)(rowBase + r0) * (DIM / 8) + q;
    const uint4* gA1 = reinterpret_cast<const uint4*>(g_Gb) + (size_t)(rowBase + r1) * (DIM / 8) + q;
    const uint4* gB0 = reinterpret_cast<const uint4*>(g_Gb) + (size_t)(colBase + r0) * (DIM / 8) + q;
    const uint4* gB1 = reinterpret_cast<const uint4*>(g_Gb) + (size_t)(colBase + r1) * (DIM / 8) + q;

    uint32_t dA0[2], dA1[2], dB0[2], dB1[2];
#pragma unroll
    for (int s = 0; s < 2; s++) {
        dA0[s] = (uint32_t)__cvta_generic_to_shared(&sA[s][r0 * LDA + q * 8]);
        dA1[s] = (uint32_t)__cvta_generic_to_shared(&sA[s][r1 * LDA + q * 8]);
        dB0[s] = (uint32_t)__cvta_generic_to_shared(&sB[s][r0 * LDA + q * 8]);
        dB1[s] = (uint32_t)__cvta_generic_to_shared(&sB[s][r1 * LDA + q * 8]);
    }

    cp16(dA0[0], gA0); cp16(dA1[0], gA1);
    cp16(dB0[0], gB0); cp16(dB1[0], gB1);
    CP_COMMIT();

    const int KT = DIM / BK;
    const int aRow = wm * 64 + (lane & 15);
    const int aCol = (lane >> 4) << 3;
    const int bRow = wn * 32 + (lane & 7);
    const int bCol = ((lane >> 3) & 1) << 3;

    for (int kt = 0; kt < KT; kt++) {
        const int cur = kt & 1;
        if (kt + 1 < KT) {
            const int nxt = cur ^ 1;
            const int kq = (kt + 1) * 4;
            cp16(dA0[nxt], gA0 + kq); cp16(dA1[nxt], gA1 + kq);
            cp16(dB0[nxt], gB0 + kq); cp16(dB1[nxt], gB1 + kq);
            CP_COMMIT();
            CP_WAIT(1);
        } else {
            CP_WAIT(0);
        }
        __syncthreads();

        const uint32_t baseA = (uint32_t)__cvta_generic_to_shared(&sA[cur][0]);
        const uint32_t baseB = (uint32_t)__cvta_generic_to_shared(&sB[cur][0]);

#pragma unroll
        for (int kk = 0; kk < 2; kk++) {
            uint32_t af[4][4];
#pragma unroll
            for (int mt = 0; mt < 4; mt++) {
                uint32_t addr = baseA + (uint32_t)(((aRow + mt * 16) * LDA + kk * 16 + aCol) << 1);
                ldmatrix_x4(af[mt][0], af[mt][1], af[mt][2], af[mt][3], addr);
            }
            uint32_t bf[4][2];
#pragma unroll
            for (int nt = 0; nt < 4; nt++) {
                uint32_t addr = baseB + (uint32_t)(((bRow + nt * 8) * LDA + kk * 16 + bCol) << 1);
                ldmatrix_x2(bf[nt][0], bf[nt][1], addr);
            }
#pragma unroll
            for (int mt = 0; mt < 4; mt++)
#pragma unroll
                for (int nt = 0; nt < 4; nt++)
                    mma16816(acc[mt][nt], af[mt][0], af[mt][1], af[mt][2], af[mt][3],
                             bf[nt][0], bf[nt][1]);
        }
        if (kt + 1 < KT) __syncthreads();
    }

    // ---------- epilogue ----------
    // log(exp(s)+eps) == s + log1p(eps*exp(-s)); correction <= 2.2e-4 worst case,
    // ~1e-8 typical -> use lg = s directly (removes all logf).
    const int g = lane >> 2;
    const int tl = lane & 3;

    float wv[4][2];
    int   cl[4][2];
    int   kc[4][2];
#pragma unroll
    for (int nt = 0; nt < 4; nt++)
#pragma unroll
        for (int j = 0; j < 2; j++) {
            int k = colBase + wn * 32 + nt * 8 + tl * 2 + j;
            kc[nt][j] = k;
            wv[nt][j] = g_w[k];
            cl[nt][j] = g_cls[k];
        }

    float cds[4][2], cps[4][2];
#pragma unroll
    for (int nt = 0; nt < 4; nt++)
#pragma unroll
        for (int j = 0; j < 2; j++) { cds[nt][j] = 0.0f; cps[nt][j] = 0.0f; }

#pragma unroll
    for (int mt = 0; mt < 4; mt++) {
#pragma unroll
        for (int h = 0; h < 2; h++) {
            const int lr = wm * 64 + mt * 16 + g + h * 8;
            const int i  = rowBase + lr;
            const int ti = g_cls[i];
            const float wr = sWr[lr];
            float ds = 0.0f, ps = 0.0f;
#pragma unroll
            for (int nt = 0; nt < 4; nt++)
#pragma unroll
                for (int j = 0; j < 2; j++) {
                    const float s = acc[mt][nt][h * 2 + j] * TAU_INV;
                    const float e = __expf(s);
                    ds += e * wv[nt][j];
                    float lg = 0.0f;
                    if (cl[nt][j] == ti && kc[nt][j] != i) lg = s;
                    ps += lg;
                    if (doTrans) {
                        cds[nt][j] += e * wr;
                        cps[nt][j] += lg;
                    }
                }
            ds += __shfl_xor_sync(0xffffffffu, ds, 1);
            ds += __shfl_xor_sync(0xffffffffu, ds, 2);
            ps += __shfl_xor_sync(0xffffffffu, ps, 1);
            ps += __shfl_xor_sync(0xffffffffu, ps, 2);
            if (tl == 0) {
                atomicAdd(&red_d[lr], ds);
                atomicAdd(&red_p[lr], ps);
            }
        }
    }

    if (doTrans) {
#pragma unroll
        for (int nt = 0; nt < 4; nt++)
#pragma unroll
            for (int j = 0; j < 2; j++) {
                float v = cds[nt][j], p = cps[nt][j];
                v += __shfl_xor_sync(0xffffffffu, v, 4);
                v += __shfl_xor_sync(0xffffffffu, v, 8);
                v += __shfl_xor_sync(0xffffffffu, v, 16);
                p += __shfl_xor_sync(0xffffffffu, p, 4);
                p += __shfl_xor_sync(0xffffffffu, p, 8);
                p += __shfl_xor_sync(0xffffffffu, p, 16);
                if (g == 0) {
                    const int ck = wn * 32 + nt * 8 + tl * 2 + j;
                    atomicAdd(&cred_d[ck], v);
                    atomicAdd(&cred_p[ck], p);
                }
            }
    }
    __syncthreads();

    if (tid < BM) {
        g_dpart[bn * BATCH + rowBase + tid] = red_d[tid];
        g_ppart[bn * BATCH + rowBase + tid] = red_p[tid];
        if (doTrans) {
            g_dpart[bm * BATCH + colBase + tid] = cred_d[tid];
            g_ppart[bm * BATCH + colBase + tid] = cred_p[tid];
        }
    }
}

// ---------------- finalize stage 1: per-row, spread across 64 SMs ----------------
__global__ void k_final1(const int* __restrict__ targets) {
    const int r = blockIdx.x * blockDim.x + threadIdx.x;   // one row per thread
    if (r >= BATCH) return;
    float d = 0.0f, p = 0.0f;
#pragma unroll
    for (int b = 0; b < NBLK; b++) {
        d += g_dpart[b * BATCH + r];
        p += g_ppart[b * BATCH + r];
    }
    const float np = (float)g_counts[targets[r]];
    g_rowv[r] = logf(d + EPSF) - p / np;
}

// ---------------- finalize stage 2: deterministic tree reduce ----------------
__global__ void k_final2(float* __restrict__ out) {
    __shared__ float sred[1024];
    const int tid = threadIdx.x;
    float local = 0.0f;
    for (int r = tid; r < BATCH; r += 1024) local += g_rowv[r];
    sred[tid] = local;
    __syncthreads();
    for (int s = 512; s > 0; s >>= 1) {
        if (tid < s) sred[tid] += sred[tid + s];
        __syncthreads();
    }
    if (tid == 0) out[0] = sred[0] / (float)BATCH;
}

// ---------------- launch ----------------
extern "C" void kernel_launch(void* const* d_in, const int* in_sizes, int n_in,
                              void* d_out, int out_size) {
    const float* centers  = nullptr;
    const float* features = nullptr;
    const int*   targets  = nullptr;
    for (int i = 0; i < n_in; i++) {
        if (in_sizes[i] == BATCH)            targets  = (const int*)d_in[i];
        else if (in_sizes[i] == BATCH * DIM) features = (const float*)d_in[i];
        else if (in_sizes[i] == NC * DIM)    centers  = (const float*)d_in[i];
    }

    k_prep<<<1, 1024>>>(targets);
    k_convert<<<(NPAD * DIM / 16 + 255) / 256, 256>>>(features, centers);

    k_gemm<<<NTILE, 256>>>();

    k_final1<<<BATCH / 64, 64>>>(targets);   // 64 blocks -> 64 SMs, latency hidden
    k_final2<<<1, 1024>>>((float*)d_out);
}